// round 3
// baseline (speedup 1.0000x reference)
#include <cuda_runtime.h>
#include <cstdint>
#include <cstddef>

#define MAX_N 100000
#define OUTF 64
#define INF 128

// Scratch (allocation-free rule: __device__ globals). 16B alignment for float4/red.v4.
__device__ __align__(16) float g_messages[(size_t)MAX_N * OUTF];
__device__ __align__(16) float g_alpha_src[MAX_N];
__device__ __align__(16) float g_alpha_dst[MAX_N];
__device__ __align__(16) float g_denom[MAX_N];
__device__ int g_ei_is64;

// ---------------------------------------------------------------------------
// Detect edge_index dtype. For little-endian int64 values in [0, 2^31), every
// odd 32-bit word is zero. For int32 random indices, essentially never.
// ---------------------------------------------------------------------------
__global__ void detect_kernel(const int* __restrict__ ei32) {
    int is64 = 1;
#pragma unroll
    for (int i = 1; i < 64; i += 2)
        if (ei32[i] != 0) { is64 = 0; break; }
    g_ei_is64 = is64;
}

// ---------------------------------------------------------------------------
// Zero agg (d_out) and denom. n_out4 = N*64/4 float4s.
// ---------------------------------------------------------------------------
__global__ void zero_kernel(float* __restrict__ out, int n_out4, int N) {
    int i = blockIdx.x * blockDim.x + threadIdx.x;
    if (i < n_out4) reinterpret_cast<float4*>(out)[i] = make_float4(0.f, 0.f, 0.f, 0.f);
    if (i < N) g_denom[i] = 0.f;
}

// ---------------------------------------------------------------------------
// messages = x @ W^T  (N x 128 @ 128 x 64), plus per-node attention scalars:
//   alpha_dst[n] = m[n] . a[0:64],  alpha_src[n] = m[n] . a[64:128]
// Block: 256 threads, 64 nodes. Thread (tx=tid&7, ty=tid>>3) computes
// 2 nodes x 8 cols.
// ---------------------------------------------------------------------------
__global__ void gemm_kernel(const float* __restrict__ x, const float* __restrict__ W,
                            const float* __restrict__ a, int N) {
    __shared__ __align__(16) float Ws[INF][68];   // Ws[k][c] = W[c][k]
    __shared__ __align__(16) float Xs[64][33];    // k-tile of x, padded
    __shared__ float As[2 * OUTF];

    int tid = threadIdx.x;
    int tx = tid & 7;                 // col group: cols tx*8 .. tx*8+7
    int ty = tid >> 3;                // node pair 0..31
    int nodeBase = blockIdx.x * 64;

    for (int i = tid; i < OUTF * INF; i += 256) {
        int c = i >> 7;               // 0..63
        int k = i & 127;              // coalesced read of W[c][k]
        Ws[k][c] = W[i];
    }
    if (tid < 2 * OUTF) As[tid] = a[tid];

    float acc0[8], acc1[8];
#pragma unroll
    for (int j = 0; j < 8; j++) { acc0[j] = 0.f; acc1[j] = 0.f; }

    int n0 = nodeBase + ty * 2;
    int n1 = n0 + 1;

    for (int k0 = 0; k0 < INF; k0 += 32) {
        __syncthreads();
        for (int i = tid; i < 64 * 32; i += 256) {
            int n = i >> 5, kk = i & 31;
            int gn = min(nodeBase + n, N - 1);
            Xs[n][kk] = x[(size_t)gn * INF + k0 + kk];
        }
        __syncthreads();
#pragma unroll
        for (int kk = 0; kk < 32; kk++) {
            float xv0 = Xs[ty * 2][kk];
            float xv1 = Xs[ty * 2 + 1][kk];
            float4 wa = *reinterpret_cast<const float4*>(&Ws[k0 + kk][tx * 8]);
            float4 wb = *reinterpret_cast<const float4*>(&Ws[k0 + kk][tx * 8 + 4]);
            acc0[0] += xv0 * wa.x; acc0[1] += xv0 * wa.y;
            acc0[2] += xv0 * wa.z; acc0[3] += xv0 * wa.w;
            acc0[4] += xv0 * wb.x; acc0[5] += xv0 * wb.y;
            acc0[6] += xv0 * wb.z; acc0[7] += xv0 * wb.w;
            acc1[0] += xv1 * wa.x; acc1[1] += xv1 * wa.y;
            acc1[2] += xv1 * wa.z; acc1[3] += xv1 * wa.w;
            acc1[4] += xv1 * wb.x; acc1[5] += xv1 * wb.y;
            acc1[6] += xv1 * wb.z; acc1[7] += xv1 * wb.w;
        }
    }

    float pd0 = 0.f, ps0 = 0.f, pd1 = 0.f, ps1 = 0.f;
#pragma unroll
    for (int j = 0; j < 8; j++) {
        float ad = As[tx * 8 + j];
        float as = As[OUTF + tx * 8 + j];
        pd0 += acc0[j] * ad; ps0 += acc0[j] * as;
        pd1 += acc1[j] * ad; ps1 += acc1[j] * as;
    }
#pragma unroll
    for (int off = 4; off; off >>= 1) {
        pd0 += __shfl_down_sync(0xffffffffu, pd0, off, 8);
        ps0 += __shfl_down_sync(0xffffffffu, ps0, off, 8);
        pd1 += __shfl_down_sync(0xffffffffu, pd1, off, 8);
        ps1 += __shfl_down_sync(0xffffffffu, ps1, off, 8);
    }

    if (n0 < N) {
        *reinterpret_cast<float4*>(&g_messages[(size_t)n0 * OUTF + tx * 8]) =
            make_float4(acc0[0], acc0[1], acc0[2], acc0[3]);
        *reinterpret_cast<float4*>(&g_messages[(size_t)n0 * OUTF + tx * 8 + 4]) =
            make_float4(acc0[4], acc0[5], acc0[6], acc0[7]);
        if (tx == 0) { g_alpha_dst[n0] = pd0; g_alpha_src[n0] = ps0; }
    }
    if (n1 < N) {
        *reinterpret_cast<float4*>(&g_messages[(size_t)n1 * OUTF + tx * 8]) =
            make_float4(acc1[0], acc1[1], acc1[2], acc1[3]);
        *reinterpret_cast<float4*>(&g_messages[(size_t)n1 * OUTF + tx * 8 + 4]) =
            make_float4(acc1[4], acc1[5], acc1[6], acc1[7]);
        if (tx == 0) { g_alpha_dst[n1] = pd1; g_alpha_src[n1] = ps1; }
    }
}

// ---------------------------------------------------------------------------
// Edge scatter: 16 threads per edge. w = exp(leaky(ad[dst] + as[src]));
// agg[dst] += w * messages[src]  via red.global.add.v4.f32 (4 floats/thread);
// denom[dst] += w (lane 0). Index dtype (int32/int64) resolved via g_ei_is64.
// ---------------------------------------------------------------------------
__global__ void edge_kernel(const void* __restrict__ ei_raw,
                            float* __restrict__ agg, long long E) {
    long long g = (long long)blockIdx.x * blockDim.x + threadIdx.x;
    long long edge = g >> 4;
    int l = (int)(g & 15);
    bool valid = edge < E;
    long long e_idx = valid ? edge : 0;

    int s = 0, d = 0;
    float w = 0.f;
    if (l == 0) {
        if (g_ei_is64) {
            const long long* ei = (const long long*)ei_raw;
            s = (int)__ldg(ei + e_idx);
            d = (int)__ldg(ei + E + e_idx);
        } else {
            const int* ei = (const int*)ei_raw;
            s = __ldg(ei + e_idx);
            d = __ldg(ei + E + e_idx);
        }
        float e = g_alpha_dst[d] + g_alpha_src[s];
        e = (e >= 0.f) ? e : 0.01f * e;
        w = __expf(e);
    }
    s = __shfl_sync(0xffffffffu, s, 0, 16);
    d = __shfl_sync(0xffffffffu, d, 0, 16);
    w = __shfl_sync(0xffffffffu, w, 0, 16);

    if (valid) {
        const float4 m = __ldg(reinterpret_cast<const float4*>(
            g_messages + (size_t)s * OUTF + l * 4));
        float* p = agg + (size_t)d * OUTF + l * 4;
        asm volatile("red.global.add.v4.f32 [%0], {%1, %2, %3, %4};"
                     :: "l"(p), "f"(m.x * w), "f"(m.y * w), "f"(m.z * w), "f"(m.w * w)
                     : "memory");
        if (l == 0) {
            asm volatile("red.global.add.f32 [%0], %1;"
                         :: "l"(g_denom + d), "f"(w) : "memory");
        }
    }
}

// ---------------------------------------------------------------------------
// Finalize: fold in the self-loop analytically, normalize in place.
// out[i] = (agg[i] + w_self * m[i]) / max(denom[i] + w_self, 1e-6)
// ---------------------------------------------------------------------------
__global__ void finalize_kernel(float* __restrict__ out, int N) {
    int g = blockIdx.x * blockDim.x + threadIdx.x;
    int i = g >> 4;
    int l = g & 15;
    if (i >= N) return;
    float e = g_alpha_dst[i] + g_alpha_src[i];
    e = (e >= 0.f) ? e : 0.01f * e;
    float ws = __expf(e);
    float den = fmaxf(g_denom[i] + ws, 1e-6f);
    float inv = 1.0f / den;
    float4 m = *reinterpret_cast<const float4*>(g_messages + (size_t)i * OUTF + l * 4);
    float4* po = reinterpret_cast<float4*>(out + (size_t)i * OUTF + l * 4);
    float4 o = *po;
    o.x = (o.x + ws * m.x) * inv;
    o.y = (o.y + ws * m.y) * inv;
    o.z = (o.z + ws * m.z) * inv;
    o.w = (o.w + ws * m.w) * inv;
    *po = o;
}

extern "C" void kernel_launch(void* const* d_in, const int* in_sizes, int n_in,
                              void* d_out, int out_size) {
    // Identify inputs BY SIZE (robust to metadata ordering):
    //   a          -> 128 elements
    //   W          -> 8192 elements (64*128)
    //   x          -> N*128 where N = out_size/64
    //   edge_index -> the remaining large input (2*E elements, int32 OR int64)
    const float* x = nullptr;
    const float* W = nullptr;
    const float* a = nullptr;
    const void* ei = nullptr;
    long long ei_elems = 0;

    int N = out_size / OUTF;
    long long x_elems = (long long)N * INF;

    for (int i = 0; i < n_in; i++) {
        long long sz = in_sizes[i];
        if (sz == 2 * OUTF) {
            a = (const float*)d_in[i];
        } else if (sz == (long long)OUTF * INF) {
            W = (const float*)d_in[i];
        } else if (sz == x_elems) {
            x = (const float*)d_in[i];
        } else {
            ei = d_in[i];
            ei_elems = sz;
        }
    }
    float* out = (float*)d_out;
    long long E = ei_elems / 2;

    detect_kernel<<<1, 1>>>((const int*)ei);

    int zn = N * (OUTF / 4);  // float4 count for d_out
    int zthreads = (zn > N) ? zn : N;
    zero_kernel<<<(zthreads + 255) / 256, 256>>>(out, zn, N);

    gemm_kernel<<<(N + 63) / 64, 256>>>(x, W, a, N);

    long long tot = E * 16;
    edge_kernel<<<(unsigned int)((tot + 255) / 256), 256>>>(ei, out, E);

    finalize_kernel<<<(N * 16 + 255) / 256, 256>>>(out, N);
}

// round 5
// speedup vs baseline: 1.2110x; 1.2110x over previous
#include <cuda_runtime.h>
#include <cstdint>
#include <cstddef>

#define MAX_N 131072
#define MAX_E 2000000
#define OUTF 64
#define INF 128
#define NPB 64   // nodes per gemm block

// Scratch (allocation-free rule: __device__ globals). 16B alignment for float4/red.v4.
__device__ __align__(16) float g_messages[(size_t)MAX_N * OUTF];
__device__ __align__(16) float g_alpha_src[MAX_N];
__device__ __align__(16) float g_alpha_dst[MAX_N];
__device__ __align__(16) float g_denom[MAX_N];
__device__ __align__(16) float g_w[MAX_E];
__device__ __align__(16) int2  g_sd[MAX_E];

// ---------------------------------------------------------------------------
// messages = x @ W^T  (N x 128 @ 128 x 64) + per-node attention scalars
//   alpha_dst[n] = m[n].a[0:64], alpha_src[n] = m[n].a[64:128]
// Also zeroes this block's slice of out and denom (replaces zero_kernel).
// Mapping: warp tx = tid>>5 owns output cols tx*8..tx*8+7 (W reads are
// warp-uniform -> LDS broadcast, no bank conflicts). ty = tid&31 owns nodes
// nodeBase+2*ty, +2*ty+1.
// ---------------------------------------------------------------------------
__global__ __launch_bounds__(256) void gemm_kernel(
    const float* __restrict__ x, const float* __restrict__ W,
    const float* __restrict__ a, int N, float* __restrict__ out) {
    __shared__ __align__(16) float Ws[INF][OUTF];   // Ws[k][c] = W[c][k]
    __shared__ __align__(16) float Xs[NPB][33];     // k-tile of x, padded (33 coprime 32)
    __shared__ float As[2 * OUTF];
    __shared__ float Pd[8][NPB];
    __shared__ float Ps[8][NPB];

    int tid = threadIdx.x;
    int tx = tid >> 5;                 // warp id 0..7 -> col group
    int ty = tid & 31;                 // node pair 0..31
    int nodeBase = blockIdx.x * NPB;

    // ---- zero out-slice and denom for this block's nodes (fused zero) ----
    {
        float4 z = make_float4(0.f, 0.f, 0.f, 0.f);
        int base4 = nodeBase * (OUTF / 4);
        int lim4 = N * (OUTF / 4);
        for (int i = tid; i < NPB * (OUTF / 4); i += 256) {
            int gidx = base4 + i;
            if (gidx < lim4) reinterpret_cast<float4*>(out)[gidx] = z;
        }
        if (tid < NPB) {
            int n = nodeBase + tid;
            if (n < N) g_denom[n] = 0.f;
        }
    }

    // ---- stage W transposed (coalesced gmem read) ----
    for (int i = tid; i < OUTF * INF; i += 256) {
        int c = i >> 7;                // 0..63
        int k = i & 127;
        Ws[k][c] = W[i];
    }
    if (tid < 2 * OUTF) As[tid] = a[tid];

    float acc0[8], acc1[8];
#pragma unroll
    for (int j = 0; j < 8; j++) { acc0[j] = 0.f; acc1[j] = 0.f; }

    int n0 = nodeBase + ty * 2;
    int n1 = n0 + 1;

    for (int k0 = 0; k0 < INF; k0 += 32) {
        __syncthreads();
        // fill Xs: warp covers one node's 32 k-values -> fully coalesced 128B
        for (int i = tid; i < NPB * 32; i += 256) {
            int n = i >> 5, kk = i & 31;
            int gn = min(nodeBase + n, N - 1);
            Xs[n][kk] = x[(size_t)gn * INF + k0 + kk];
        }
        __syncthreads();
#pragma unroll
        for (int kk = 0; kk < 32; kk++) {
            // warp-uniform -> broadcast, 1 wavefront each
            float4 wa = *reinterpret_cast<const float4*>(&Ws[k0 + kk][tx * 8]);
            float4 wb = *reinterpret_cast<const float4*>(&Ws[k0 + kk][tx * 8 + 4]);
            float xv0 = Xs[ty * 2][kk];       // conflict-free (stride 33)
            float xv1 = Xs[ty * 2 + 1][kk];
            acc0[0] += xv0 * wa.x; acc0[1] += xv0 * wa.y;
            acc0[2] += xv0 * wa.z; acc0[3] += xv0 * wa.w;
            acc0[4] += xv0 * wb.x; acc0[5] += xv0 * wb.y;
            acc0[6] += xv0 * wb.z; acc0[7] += xv0 * wb.w;
            acc1[0] += xv1 * wa.x; acc1[1] += xv1 * wa.y;
            acc1[2] += xv1 * wa.z; acc1[3] += xv1 * wa.w;
            acc1[4] += xv1 * wb.x; acc1[5] += xv1 * wb.y;
            acc1[6] += xv1 * wb.z; acc1[7] += xv1 * wb.w;
        }
    }

    // ---- alpha partials: this thread's 8 cols; reduce across the 8 warps ----
    float pd0 = 0.f, ps0 = 0.f, pd1 = 0.f, ps1 = 0.f;
#pragma unroll
    for (int j = 0; j < 8; j++) {
        float ad = As[tx * 8 + j];          // warp-uniform broadcast
        float as = As[OUTF + tx * 8 + j];
        pd0 += acc0[j] * ad; ps0 += acc0[j] * as;
        pd1 += acc1[j] * ad; ps1 += acc1[j] * as;
    }
    Pd[tx][ty * 2] = pd0;     Ps[tx][ty * 2] = ps0;
    Pd[tx][ty * 2 + 1] = pd1; Ps[tx][ty * 2 + 1] = ps1;

    // ---- store messages ----
    if (n0 < N) {
        *reinterpret_cast<float4*>(&g_messages[(size_t)n0 * OUTF + tx * 8]) =
            make_float4(acc0[0], acc0[1], acc0[2], acc0[3]);
        *reinterpret_cast<float4*>(&g_messages[(size_t)n0 * OUTF + tx * 8 + 4]) =
            make_float4(acc0[4], acc0[5], acc0[6], acc0[7]);
    }
    if (n1 < N) {
        *reinterpret_cast<float4*>(&g_messages[(size_t)n1 * OUTF + tx * 8]) =
            make_float4(acc1[0], acc1[1], acc1[2], acc1[3]);
        *reinterpret_cast<float4*>(&g_messages[(size_t)n1 * OUTF + tx * 8 + 4]) =
            make_float4(acc1[4], acc1[5], acc1[6], acc1[7]);
    }

    __syncthreads();
    if (tid < NPB) {
        float sd = 0.f, ss = 0.f;
#pragma unroll
        for (int wg = 0; wg < 8; wg++) { sd += Pd[wg][tid]; ss += Ps[wg][tid]; }
        int n = nodeBase + tid;
        if (n < N) { g_alpha_dst[n] = sd; g_alpha_src[n] = ss; }
    }
}

// ---------------------------------------------------------------------------
// Per-edge weights: 1 thread/edge, coalesced. Packs (s,d) to int2 + w float.
// Edge-index dtype (int32 vs int64) sniffed inline from the first odd words.
// ---------------------------------------------------------------------------
__global__ void weight_kernel(const void* __restrict__ ei_raw, long long E) {
    const int* ei32 = (const int*)ei_raw;
    // int64 little-endian values < 2^31 -> odd words all zero (L1 broadcast)
    bool is64 = (ei32[1] == 0) & (ei32[3] == 0) & (ei32[5] == 0) & (ei32[7] == 0);

    long long i = (long long)blockIdx.x * blockDim.x + threadIdx.x;
    if (i >= E || i >= MAX_E) return;
    int s, d;
    if (is64) {
        const long long* e64 = (const long long*)ei_raw;
        s = (int)__ldg(e64 + i);
        d = (int)__ldg(e64 + E + i);
    } else {
        s = __ldg(ei32 + i);
        d = __ldg(ei32 + E + i);
    }
    float e = g_alpha_dst[d] + g_alpha_src[s];
    e = (e >= 0.f) ? e : 0.01f * e;
    g_w[i] = __expf(e);
    g_sd[i] = make_int2(s, d);
}

// ---------------------------------------------------------------------------
// Edge scatter: 16 threads per edge, 2 edges per thread (MLP=2).
// All 16 lanes read the same (s,d,w) -> L1 broadcast, no shuffles.
// agg[dst] += w * messages[src] via red.global.add.v4.f32; denom via lane 0.
// ---------------------------------------------------------------------------
__global__ void scatter_kernel(float* __restrict__ agg, long long E) {
    long long g = (long long)blockIdx.x * blockDim.x + threadIdx.x;
    long long pair = g >> 4;
    int l = (int)(g & 15);
    long long e0 = pair * 2;
    if (e0 >= E) return;
    long long e1 = e0 + 1;
    bool v1 = e1 < E;

    int2 sd0 = __ldg(&g_sd[e0]);
    float w0 = __ldg(&g_w[e0]);
    int2 sd1 = sd0; float w1 = 0.f;
    if (v1) { sd1 = __ldg(&g_sd[e1]); w1 = __ldg(&g_w[e1]); }

    // two independent gathers in flight
    const float4 m0 = __ldg(reinterpret_cast<const float4*>(
        g_messages + (size_t)sd0.x * OUTF + l * 4));
    float4 m1 = make_float4(0.f, 0.f, 0.f, 0.f);
    if (v1) m1 = __ldg(reinterpret_cast<const float4*>(
        g_messages + (size_t)sd1.x * OUTF + l * 4));

    float* p0 = agg + (size_t)sd0.y * OUTF + l * 4;
    asm volatile("red.global.add.v4.f32 [%0], {%1, %2, %3, %4};"
                 :: "l"(p0), "f"(m0.x * w0), "f"(m0.y * w0), "f"(m0.z * w0), "f"(m0.w * w0)
                 : "memory");
    if (v1) {
        float* p1 = agg + (size_t)sd1.y * OUTF + l * 4;
        asm volatile("red.global.add.v4.f32 [%0], {%1, %2, %3, %4};"
                     :: "l"(p1), "f"(m1.x * w1), "f"(m1.y * w1), "f"(m1.z * w1), "f"(m1.w * w1)
                     : "memory");
    }
    if (l == 0) {
        asm volatile("red.global.add.f32 [%0], %1;"
                     :: "l"(g_denom + sd0.y), "f"(w0) : "memory");
        if (v1)
            asm volatile("red.global.add.f32 [%0], %1;"
                         :: "l"(g_denom + sd1.y), "f"(w1) : "memory");
    }
}

// ---------------------------------------------------------------------------
// Finalize: fold in the self-loop analytically, normalize in place.
// out[i] = (agg[i] + w_self * m[i]) / max(denom[i] + w_self, 1e-6)
// ---------------------------------------------------------------------------
__global__ void finalize_kernel(float* __restrict__ out, int N) {
    int g = blockIdx.x * blockDim.x + threadIdx.x;
    int i = g >> 4;
    int l = g & 15;
    if (i >= N) return;
    float e = g_alpha_dst[i] + g_alpha_src[i];
    e = (e >= 0.f) ? e : 0.01f * e;
    float ws = __expf(e);
    float den = fmaxf(g_denom[i] + ws, 1e-6f);
    float inv = 1.0f / den;
    float4 m = *reinterpret_cast<const float4*>(g_messages + (size_t)i * OUTF + l * 4);
    float4* po = reinterpret_cast<float4*>(out + (size_t)i * OUTF + l * 4);
    float4 o = *po;
    o.x = (o.x + ws * m.x) * inv;
    o.y = (o.y + ws * m.y) * inv;
    o.z = (o.z + ws * m.z) * inv;
    o.w = (o.w + ws * m.w) * inv;
    *po = o;
}

extern "C" void kernel_launch(void* const* d_in, const int* in_sizes, int n_in,
                              void* d_out, int out_size) {
    // Identify inputs BY SIZE (robust to metadata ordering):
    //   a -> 128, W -> 8192, x -> N*128 (== 2*out_size), edge_index -> rest
    const float* x = nullptr;
    const float* W = nullptr;
    const float* a = nullptr;
    const void* ei = nullptr;
    long long ei_elems = 0;

    int N = out_size / OUTF;
    long long x_elems = (long long)N * INF;

    for (int i = 0; i < n_in; i++) {
        long long sz = in_sizes[i];
        if (sz == 2 * OUTF) {
            a = (const float*)d_in[i];
        } else if (sz == (long long)OUTF * INF) {
            W = (const float*)d_in[i];
        } else if (sz == x_elems) {
            x = (const float*)d_in[i];
        } else {
            ei = d_in[i];
            ei_elems = sz;
        }
    }
    float* out = (float*)d_out;
    long long E = ei_elems / 2;
    if (E > MAX_E) E = MAX_E;

    gemm_kernel<<<(N + NPB - 1) / NPB, 256>>>(x, W, a, N, out);

    weight_kernel<<<(unsigned int)((E + 255) / 256), 256>>>(ei, E);

    long long pairs = (E + 1) / 2;
    long long sthreads = pairs * 16;
    scatter_kernel<<<(unsigned int)((sthreads + 255) / 256), 256>>>(out, E);

    finalize_kernel<<<(N * 16 + 255) / 256, 256>>>(out, N);
}

// round 7
// speedup vs baseline: 1.2572x; 1.0381x over previous
#include <cuda_runtime.h>
#include <cuda_fp16.h>
#include <cstdint>
#include <cstddef>

#define MAX_N 131072
#define MAX_E 2000000
#define OUTF 64
#define INF 128
#define NPB 64   // nodes per gemm block

// Scratch (allocation-free rule: __device__ globals). 16B alignment for vector ops.
__device__ __align__(16) __half g_msg_h[(size_t)MAX_N * OUTF];   // fp16 messages
__device__ __align__(16) float g_alpha_src[MAX_N];
__device__ __align__(16) float g_alpha_dst[MAX_N];
__device__ __align__(16) float g_denom[MAX_N];
__device__ __align__(16) float g_meta[(size_t)MAX_E * 4];        // (w, s-bits, d-bits, 0)

static __device__ __forceinline__ unsigned h2_bits(__half2 h) {
    return *reinterpret_cast<unsigned*>(&h);
}

// ---------------------------------------------------------------------------
// messages = x @ W^T  (N x 128 @ 128 x 64) + per-node attention scalars
//   alpha_dst[n] = m[n].a[0:64], alpha_src[n] = m[n].a[64:128]
// Zeroes this block's out-slice and denom. Messages stored fp16.
// Warp tx = tid>>5 owns cols tx*8..+7 (W reads warp-uniform -> broadcast);
// ty = tid&31 owns nodes nodeBase+2*ty, +2*ty+1.
// ---------------------------------------------------------------------------
__global__ __launch_bounds__(256) void gemm_kernel(
    const float* __restrict__ x, const float* __restrict__ W,
    const float* __restrict__ a, int N, float* __restrict__ out) {
    __shared__ __align__(16) float Ws[INF][OUTF];   // Ws[k][c] = W[c][k]
    __shared__ __align__(16) float Xs[NPB][33];     // k-tile of x, padded
    __shared__ float As[2 * OUTF];
    __shared__ float Pd[8][NPB];
    __shared__ float Ps[8][NPB];

    int tid = threadIdx.x;
    int tx = tid >> 5;
    int ty = tid & 31;
    int nodeBase = blockIdx.x * NPB;

    // ---- zero out-slice and denom (fused zero) ----
    {
        float4 z = make_float4(0.f, 0.f, 0.f, 0.f);
        int base4 = nodeBase * (OUTF / 4);
        int lim4 = N * (OUTF / 4);
        for (int i = tid; i < NPB * (OUTF / 4); i += 256) {
            int gidx = base4 + i;
            if (gidx < lim4) reinterpret_cast<float4*>(out)[gidx] = z;
        }
        if (tid < NPB) {
            int n = nodeBase + tid;
            if (n < N) g_denom[n] = 0.f;
        }
    }

    // ---- stage W transposed (coalesced gmem read) ----
    for (int i = tid; i < OUTF * INF; i += 256) {
        int c = i >> 7;
        int k = i & 127;
        Ws[k][c] = W[i];
    }
    if (tid < 2 * OUTF) As[tid] = a[tid];

    float acc0[8], acc1[8];
#pragma unroll
    for (int j = 0; j < 8; j++) { acc0[j] = 0.f; acc1[j] = 0.f; }

    int n0 = nodeBase + ty * 2;
    int n1 = n0 + 1;

    for (int k0 = 0; k0 < INF; k0 += 32) {
        __syncthreads();
        for (int i = tid; i < NPB * 32; i += 256) {
            int n = i >> 5, kk = i & 31;
            int gn = min(nodeBase + n, N - 1);
            Xs[n][kk] = x[(size_t)gn * INF + k0 + kk];
        }
        __syncthreads();
#pragma unroll
        for (int kk = 0; kk < 32; kk++) {
            float4 wa = *reinterpret_cast<const float4*>(&Ws[k0 + kk][tx * 8]);
            float4 wb = *reinterpret_cast<const float4*>(&Ws[k0 + kk][tx * 8 + 4]);
            float xv0 = Xs[ty * 2][kk];
            float xv1 = Xs[ty * 2 + 1][kk];
            acc0[0] += xv0 * wa.x; acc0[1] += xv0 * wa.y;
            acc0[2] += xv0 * wa.z; acc0[3] += xv0 * wa.w;
            acc0[4] += xv0 * wb.x; acc0[5] += xv0 * wb.y;
            acc0[6] += xv0 * wb.z; acc0[7] += xv0 * wb.w;
            acc1[0] += xv1 * wa.x; acc1[1] += xv1 * wa.y;
            acc1[2] += xv1 * wa.z; acc1[3] += xv1 * wa.w;
            acc1[4] += xv1 * wb.x; acc1[5] += xv1 * wb.y;
            acc1[6] += xv1 * wb.z; acc1[7] += xv1 * wb.w;
        }
    }

    // ---- alpha partials over this thread's 8 cols; reduce across 8 warps ----
    float pd0 = 0.f, ps0 = 0.f, pd1 = 0.f, ps1 = 0.f;
#pragma unroll
    for (int j = 0; j < 8; j++) {
        float ad = As[tx * 8 + j];
        float as = As[OUTF + tx * 8 + j];
        pd0 += acc0[j] * ad; ps0 += acc0[j] * as;
        pd1 += acc1[j] * ad; ps1 += acc1[j] * as;
    }
    Pd[tx][ty * 2] = pd0;     Ps[tx][ty * 2] = ps0;
    Pd[tx][ty * 2 + 1] = pd1; Ps[tx][ty * 2 + 1] = ps1;

    // ---- store messages as fp16 (one 16B store per node-slice) ----
    if (n0 < N) {
        uint4 v = make_uint4(h2_bits(__floats2half2_rn(acc0[0], acc0[1])),
                             h2_bits(__floats2half2_rn(acc0[2], acc0[3])),
                             h2_bits(__floats2half2_rn(acc0[4], acc0[5])),
                             h2_bits(__floats2half2_rn(acc0[6], acc0[7])));
        *reinterpret_cast<uint4*>(g_msg_h + (size_t)n0 * OUTF + tx * 8) = v;
    }
    if (n1 < N) {
        uint4 v = make_uint4(h2_bits(__floats2half2_rn(acc1[0], acc1[1])),
                             h2_bits(__floats2half2_rn(acc1[2], acc1[3])),
                             h2_bits(__floats2half2_rn(acc1[4], acc1[5])),
                             h2_bits(__floats2half2_rn(acc1[6], acc1[7])));
        *reinterpret_cast<uint4*>(g_msg_h + (size_t)n1 * OUTF + tx * 8) = v;
    }

    __syncthreads();
    if (tid < NPB) {
        float sd = 0.f, ss = 0.f;
#pragma unroll
        for (int wg = 0; wg < 8; wg++) { sd += Pd[wg][tid]; ss += Ps[wg][tid]; }
        int n = nodeBase + tid;
        if (n < N) { g_alpha_dst[n] = sd; g_alpha_src[n] = ss; }
    }
}

// ---------------------------------------------------------------------------
// Per-edge weights: 1 thread/edge, coalesced. Packs (w, s, d, 0) into one
// 16B record. Edge-index dtype (int32 vs int64) sniffed inline.
// ---------------------------------------------------------------------------
__global__ void weight_kernel(const void* __restrict__ ei_raw, long long E) {
    const int* ei32 = (const int*)ei_raw;
    bool is64 = (ei32[1] == 0) & (ei32[3] == 0) & (ei32[5] == 0) & (ei32[7] == 0);

    long long i = (long long)blockIdx.x * blockDim.x + threadIdx.x;
    if (i >= E || i >= MAX_E) return;
    int s, d;
    if (is64) {
        const long long* e64 = (const long long*)ei_raw;
        s = (int)__ldg(e64 + i);
        d = (int)__ldg(e64 + E + i);
    } else {
        s = __ldg(ei32 + i);
        d = __ldg(ei32 + E + i);
    }
    float e = g_alpha_dst[d] + g_alpha_src[s];
    e = (e >= 0.f) ? e : 0.01f * e;
    float w = __expf(e);
    *reinterpret_cast<float4*>(g_meta + (size_t)i * 4) =
        make_float4(w, __int_as_float(s), __int_as_float(d), 0.f);
}

// ---------------------------------------------------------------------------
// Edge scatter: 16 threads/edge, 2 edges/thread (MLP=2).
// All 16 lanes broadcast-read one 16B meta record. Gather is fp16 (8B/lane,
// 4 sectors/edge); accumulate via fp32 red.global.add.v4.
// ---------------------------------------------------------------------------
__global__ void scatter_kernel(float* __restrict__ agg, long long E) {
    long long g = (long long)blockIdx.x * blockDim.x + threadIdx.x;
    long long pair = g >> 4;
    int l = (int)(g & 15);
    long long e0 = pair * 2;
    if (e0 >= E) return;
    long long e1 = e0 + 1;
    bool v1 = e1 < E;

    float4 mt0 = __ldg(reinterpret_cast<const float4*>(g_meta + (size_t)e0 * 4));
    float4 mt1 = mt0;
    if (v1) mt1 = __ldg(reinterpret_cast<const float4*>(g_meta + (size_t)e1 * 4));
    int s0 = __float_as_int(mt0.y), d0 = __float_as_int(mt0.z);
    int s1 = __float_as_int(mt1.y), d1 = __float_as_int(mt1.z);
    float w0 = mt0.x, w1 = mt1.x;

    // two independent fp16 gathers in flight (8B each)
    uint2 q0 = __ldg(reinterpret_cast<const uint2*>(
        g_msg_h + (size_t)s0 * OUTF + l * 4));
    uint2 q1 = make_uint2(0u, 0u);
    if (v1) q1 = __ldg(reinterpret_cast<const uint2*>(
        g_msg_h + (size_t)s1 * OUTF + l * 4));

    float2 f0a = __half22float2(*reinterpret_cast<__half2*>(&q0.x));
    float2 f0b = __half22float2(*reinterpret_cast<__half2*>(&q0.y));
    float* p0 = agg + (size_t)d0 * OUTF + l * 4;
    asm volatile("red.global.add.v4.f32 [%0], {%1, %2, %3, %4};"
                 :: "l"(p0), "f"(f0a.x * w0), "f"(f0a.y * w0),
                    "f"(f0b.x * w0), "f"(f0b.y * w0)
                 : "memory");
    if (v1) {
        float2 f1a = __half22float2(*reinterpret_cast<__half2*>(&q1.x));
        float2 f1b = __half22float2(*reinterpret_cast<__half2*>(&q1.y));
        float* p1 = agg + (size_t)d1 * OUTF + l * 4;
        asm volatile("red.global.add.v4.f32 [%0], {%1, %2, %3, %4};"
                     :: "l"(p1), "f"(f1a.x * w1), "f"(f1a.y * w1),
                        "f"(f1b.x * w1), "f"(f1b.y * w1)
                     : "memory");
    }
    if (l == 0) {
        asm volatile("red.global.add.f32 [%0], %1;"
                     :: "l"(g_denom + d0), "f"(w0) : "memory");
        if (v1)
            asm volatile("red.global.add.f32 [%0], %1;"
                         :: "l"(g_denom + d1), "f"(w1) : "memory");
    }
}

// ---------------------------------------------------------------------------
// Finalize: fold in the self-loop analytically, normalize in place.
// out[i] = (agg[i] + w_self * m[i]) / max(denom[i] + w_self, 1e-6)
// ---------------------------------------------------------------------------
__global__ void finalize_kernel(float* __restrict__ out, int N) {
    int g = blockIdx.x * blockDim.x + threadIdx.x;
    int i = g >> 4;
    int l = g & 15;
    if (i >= N) return;
    float e = g_alpha_dst[i] + g_alpha_src[i];
    e = (e >= 0.f) ? e : 0.01f * e;
    float ws = __expf(e);
    float den = fmaxf(g_denom[i] + ws, 1e-6f);
    float inv = 1.0f / den;
    uint2 q = *reinterpret_cast<const uint2*>(g_msg_h + (size_t)i * OUTF + l * 4);
    float2 ma = __half22float2(*reinterpret_cast<__half2*>(&q.x));
    float2 mb = __half22float2(*reinterpret_cast<__half2*>(&q.y));
    float4* po = reinterpret_cast<float4*>(out + (size_t)i * OUTF + l * 4);
    float4 o = *po;
    o.x = (o.x + ws * ma.x) * inv;
    o.y = (o.y + ws * ma.y) * inv;
    o.z = (o.z + ws * mb.x) * inv;
    o.w = (o.w + ws * mb.y) * inv;
    *po = o;
}

extern "C" void kernel_launch(void* const* d_in, const int* in_sizes, int n_in,
                              void* d_out, int out_size) {
    // Identify inputs BY SIZE:
    //   a -> 128, W -> 8192, x -> N*128 (== 2*out_size), edge_index -> rest
    const float* x = nullptr;
    const float* W = nullptr;
    const float* a = nullptr;
    const void* ei = nullptr;
    long long ei_elems = 0;

    int N = out_size / OUTF;
    long long x_elems = (long long)N * INF;

    for (int i = 0; i < n_in; i++) {
        long long sz = in_sizes[i];
        if (sz == 2 * OUTF) {
            a = (const float*)d_in[i];
        } else if (sz == (long long)OUTF * INF) {
            W = (const float*)d_in[i];
        } else if (sz == x_elems) {
            x = (const float*)d_in[i];
        } else {
            ei = d_in[i];
            ei_elems = sz;
        }
    }
    float* out = (float*)d_out;
    long long E = ei_elems / 2;
    if (E > MAX_E) E = MAX_E;

    gemm_kernel<<<(N + NPB - 1) / NPB, 256>>>(x, W, a, N, out);

    weight_kernel<<<(unsigned int)((E + 255) / 256), 256>>>(ei, E);

    long long pairs = (E + 1) / 2;
    long long sthreads = pairs * 16;
    scatter_kernel<<<(unsigned int)((sthreads + 255) / 256), 256>>>(out, E);

    finalize_kernel<<<(N * 16 + 255) / 256, 256>>>(out, N);
}

// round 8
// speedup vs baseline: 1.3330x; 1.0603x over previous
#include <cuda_runtime.h>
#include <cuda_fp16.h>
#include <cstdint>
#include <cstddef>

#define MAX_N 131072
#define MAX_E 2000000
#define OUTF 64
#define INF 128
#define NPB 64   // nodes per gemm block

// Scratch (allocation-free rule: __device__ globals).
__device__ __align__(16) __half g_msg_h[(size_t)MAX_N * OUTF];   // fp16 messages
__device__ __align__(16) float g_alpha_src[MAX_N];
__device__ __align__(16) float g_alpha_dst[MAX_N];
__device__ __align__(16) float g_w[MAX_E];
__device__ __align__(16) int2  g_sd[MAX_E];
__device__ __align__(16) float2 g_sorted[MAX_E];   // (w, s-bits) in dst-sorted order
__device__ __align__(16) int g_hist[MAX_N];
__device__ __align__(16) int g_start[MAX_N];
__device__ __align__(16) int g_cursor[MAX_N];
__device__ __align__(16) int g_bsum[512];

static __device__ __forceinline__ unsigned h2_bits(__half2 h) {
    return *reinterpret_cast<unsigned*>(&h);
}

// ---------------------------------------------------------------------------
// messages = x @ W^T (fp16 out) + per-node attention scalars. Zeroes g_hist.
// ---------------------------------------------------------------------------
__global__ __launch_bounds__(256) void gemm_kernel(
    const float* __restrict__ x, const float* __restrict__ W,
    const float* __restrict__ a, int N) {
    __shared__ __align__(16) float Ws[INF][OUTF];   // Ws[k][c] = W[c][k]
    __shared__ __align__(16) float Xs[NPB][33];
    __shared__ float As[2 * OUTF];
    __shared__ float Pd[8][NPB];
    __shared__ float Ps[8][NPB];

    int tid = threadIdx.x;
    int tx = tid >> 5;
    int ty = tid & 31;
    int nodeBase = blockIdx.x * NPB;

    if (tid < NPB) {
        int n = nodeBase + tid;
        if (n < N) g_hist[n] = 0;
    }

    for (int i = tid; i < OUTF * INF; i += 256) {
        int c = i >> 7;
        int k = i & 127;
        Ws[k][c] = W[i];
    }
    if (tid < 2 * OUTF) As[tid] = a[tid];

    float acc0[8], acc1[8];
#pragma unroll
    for (int j = 0; j < 8; j++) { acc0[j] = 0.f; acc1[j] = 0.f; }

    int n0 = nodeBase + ty * 2;
    int n1 = n0 + 1;

    for (int k0 = 0; k0 < INF; k0 += 32) {
        __syncthreads();
        for (int i = tid; i < NPB * 32; i += 256) {
            int n = i >> 5, kk = i & 31;
            int gn = min(nodeBase + n, N - 1);
            Xs[n][kk] = x[(size_t)gn * INF + k0 + kk];
        }
        __syncthreads();
#pragma unroll
        for (int kk = 0; kk < 32; kk++) {
            float4 wa = *reinterpret_cast<const float4*>(&Ws[k0 + kk][tx * 8]);
            float4 wb = *reinterpret_cast<const float4*>(&Ws[k0 + kk][tx * 8 + 4]);
            float xv0 = Xs[ty * 2][kk];
            float xv1 = Xs[ty * 2 + 1][kk];
            acc0[0] += xv0 * wa.x; acc0[1] += xv0 * wa.y;
            acc0[2] += xv0 * wa.z; acc0[3] += xv0 * wa.w;
            acc0[4] += xv0 * wb.x; acc0[5] += xv0 * wb.y;
            acc0[6] += xv0 * wb.z; acc0[7] += xv0 * wb.w;
            acc1[0] += xv1 * wa.x; acc1[1] += xv1 * wa.y;
            acc1[2] += xv1 * wa.z; acc1[3] += xv1 * wa.w;
            acc1[4] += xv1 * wb.x; acc1[5] += xv1 * wb.y;
            acc1[6] += xv1 * wb.z; acc1[7] += xv1 * wb.w;
        }
    }

    float pd0 = 0.f, ps0 = 0.f, pd1 = 0.f, ps1 = 0.f;
#pragma unroll
    for (int j = 0; j < 8; j++) {
        float ad = As[tx * 8 + j];
        float as = As[OUTF + tx * 8 + j];
        pd0 += acc0[j] * ad; ps0 += acc0[j] * as;
        pd1 += acc1[j] * ad; ps1 += acc1[j] * as;
    }
    Pd[tx][ty * 2] = pd0;     Ps[tx][ty * 2] = ps0;
    Pd[tx][ty * 2 + 1] = pd1; Ps[tx][ty * 2 + 1] = ps1;

    if (n0 < N) {
        uint4 v = make_uint4(h2_bits(__floats2half2_rn(acc0[0], acc0[1])),
                             h2_bits(__floats2half2_rn(acc0[2], acc0[3])),
                             h2_bits(__floats2half2_rn(acc0[4], acc0[5])),
                             h2_bits(__floats2half2_rn(acc0[6], acc0[7])));
        *reinterpret_cast<uint4*>(g_msg_h + (size_t)n0 * OUTF + tx * 8) = v;
    }
    if (n1 < N) {
        uint4 v = make_uint4(h2_bits(__floats2half2_rn(acc1[0], acc1[1])),
                             h2_bits(__floats2half2_rn(acc1[2], acc1[3])),
                             h2_bits(__floats2half2_rn(acc1[4], acc1[5])),
                             h2_bits(__floats2half2_rn(acc1[6], acc1[7])));
        *reinterpret_cast<uint4*>(g_msg_h + (size_t)n1 * OUTF + tx * 8) = v;
    }

    __syncthreads();
    if (tid < NPB) {
        float sd = 0.f, ss = 0.f;
#pragma unroll
        for (int wg = 0; wg < 8; wg++) { sd += Pd[wg][tid]; ss += Ps[wg][tid]; }
        int n = nodeBase + tid;
        if (n < N) { g_alpha_dst[n] = sd; g_alpha_src[n] = ss; }
    }
}

// ---------------------------------------------------------------------------
// Per-edge weights + dst histogram. Stages (s,d) and w coalesced.
// ---------------------------------------------------------------------------
__global__ void weight_hist_kernel(const void* __restrict__ ei_raw, long long E) {
    const int* ei32 = (const int*)ei_raw;
    bool is64 = (ei32[1] == 0) & (ei32[3] == 0) & (ei32[5] == 0) & (ei32[7] == 0);

    long long i = (long long)blockIdx.x * blockDim.x + threadIdx.x;
    if (i >= E || i >= MAX_E) return;
    int s, d;
    if (is64) {
        const long long* e64 = (const long long*)ei_raw;
        s = (int)__ldg(e64 + i);
        d = (int)__ldg(e64 + E + i);
    } else {
        s = __ldg(ei32 + i);
        d = __ldg(ei32 + E + i);
    }
    float e = g_alpha_dst[d] + g_alpha_src[s];
    e = (e >= 0.f) ? e : 0.01f * e;
    g_w[i] = __expf(e);
    g_sd[i] = make_int2(s, d);
    atomicAdd(&g_hist[d], 1);
}

// ---------------------------------------------------------------------------
// Exclusive scan of g_hist -> g_start (3 kernels; N <= 131072 -> <=128 blocks)
// ---------------------------------------------------------------------------
__global__ __launch_bounds__(256) void scan1_kernel(int N) {
    __shared__ int sh[256];
    int tid = threadIdx.x;
    int base = blockIdx.x * 1024 + tid * 4;
    int v0 = (base + 0 < N) ? g_hist[base + 0] : 0;
    int v1 = (base + 1 < N) ? g_hist[base + 1] : 0;
    int v2 = (base + 2 < N) ? g_hist[base + 2] : 0;
    int v3 = (base + 3 < N) ? g_hist[base + 3] : 0;
    int t = v0 + v1 + v2 + v3;
    sh[tid] = t;
    __syncthreads();
    for (int off = 1; off < 256; off <<= 1) {
        int x = 0;
        if (tid >= off) x = sh[tid - off];
        __syncthreads();
        if (tid >= off) sh[tid] += x;
        __syncthreads();
    }
    int run = sh[tid] - t;   // exclusive prefix of this thread's chunk
    if (base + 0 < N) g_start[base + 0] = run; run += v0;
    if (base + 1 < N) g_start[base + 1] = run; run += v1;
    if (base + 2 < N) g_start[base + 2] = run; run += v2;
    if (base + 3 < N) g_start[base + 3] = run;
    if (tid == 255) g_bsum[blockIdx.x] = sh[255];
}

__global__ void scan2_kernel(int nblk) {
    if (threadIdx.x == 0) {
        int run = 0;
        for (int i = 0; i < nblk; i++) { int t = g_bsum[i]; g_bsum[i] = run; run += t; }
    }
}

__global__ void scan3_kernel(int N) {
    int i = blockIdx.x * blockDim.x + threadIdx.x;
    if (i < N) {
        int v = g_start[i] + g_bsum[i >> 10];
        g_start[i] = v;
        g_cursor[i] = v;
    }
}

// ---------------------------------------------------------------------------
// Place edges into dst-sorted order via ticket atomics. Record = (w, s-bits).
// ---------------------------------------------------------------------------
__global__ void place_kernel(long long E) {
    long long i = (long long)blockIdx.x * blockDim.x + threadIdx.x;
    if (i >= E) return;
    int2 sd = __ldg(&g_sd[i]);
    float w = __ldg(&g_w[i]);
    int pos = atomicAdd(&g_cursor[sd.y], 1);
    g_sorted[pos] = make_float2(w, __int_as_float(sd.x));
}

// ---------------------------------------------------------------------------
// Aggregate: one warp per dst. Bucket [g_start[d], g_cursor[d]) is contiguous.
// Lane covers 2 output cols. Record reads broadcast; gather 128B coalesced;
// denominator identical across lanes (no reduce). Folds self-loop + normalize.
// ---------------------------------------------------------------------------
__global__ __launch_bounds__(256) void aggregate_kernel(float* __restrict__ out, int N) {
    int gw = (blockIdx.x * blockDim.x + threadIdx.x) >> 5;
    int lane = threadIdx.x & 31;
    if (gw >= N) return;
    int d = gw;
    int start = __ldg(&g_start[d]);
    int end = __ldg(&g_cursor[d]);

    float accx = 0.f, accy = 0.f, denom = 0.f;
    float2 r = make_float2(0.f, 0.f);
    if (start < end) r = __ldg(&g_sorted[start]);
    for (int e = start; e < end; e++) {
        float2 rn = r;
        if (e + 1 < end) rn = __ldg(&g_sorted[e + 1]);   // prefetch next record
        int s = __float_as_int(r.y);
        __half2 h = __ldg(reinterpret_cast<const __half2*>(
            g_msg_h + (size_t)s * OUTF) + lane);
        float2 f = __half22float2(h);
        accx += r.x * f.x;
        accy += r.x * f.y;
        denom += r.x;
        r = rn;
    }

    // self-loop
    float e0 = g_alpha_dst[d] + g_alpha_src[d];
    e0 = (e0 >= 0.f) ? e0 : 0.01f * e0;
    float ws = __expf(e0);
    __half2 hm = __ldg(reinterpret_cast<const __half2*>(
        g_msg_h + (size_t)d * OUTF) + lane);
    float2 fm = __half22float2(hm);
    accx += ws * fm.x;
    accy += ws * fm.y;
    denom += ws;

    float inv = 1.0f / fmaxf(denom, 1e-6f);
    reinterpret_cast<float2*>(out + (size_t)d * OUTF)[lane] =
        make_float2(accx * inv, accy * inv);
}

extern "C" void kernel_launch(void* const* d_in, const int* in_sizes, int n_in,
                              void* d_out, int out_size) {
    // Identify inputs BY SIZE:
    //   a -> 128, W -> 8192, x -> N*128 (== 2*out_size), edge_index -> rest
    const float* x = nullptr;
    const float* W = nullptr;
    const float* a = nullptr;
    const void* ei = nullptr;
    long long ei_elems = 0;

    int N = out_size / OUTF;
    long long x_elems = (long long)N * INF;

    for (int i = 0; i < n_in; i++) {
        long long sz = in_sizes[i];
        if (sz == 2 * OUTF) {
            a = (const float*)d_in[i];
        } else if (sz == (long long)OUTF * INF) {
            W = (const float*)d_in[i];
        } else if (sz == x_elems) {
            x = (const float*)d_in[i];
        } else {
            ei = d_in[i];
            ei_elems = sz;
        }
    }
    float* out = (float*)d_out;
    long long E = ei_elems / 2;
    if (E > MAX_E) E = MAX_E;

    gemm_kernel<<<(N + NPB - 1) / NPB, 256>>>(x, W, a, N);

    weight_hist_kernel<<<(unsigned int)((E + 255) / 256), 256>>>(ei, E);

    int nblk = (N + 1023) / 1024;
    scan1_kernel<<<nblk, 256>>>(N);
    scan2_kernel<<<1, 32>>>(nblk);
    scan3_kernel<<<(N + 255) / 256, 256>>>(N);

    place_kernel<<<(unsigned int)((E + 255) / 256), 256>>>(E);

    aggregate_kernel<<<(N * 32 + 255) / 256, 256>>>(out, N);
}

// round 9
// speedup vs baseline: 1.4041x; 1.0534x over previous
#include <cuda_runtime.h>
#include <cuda_fp16.h>
#include <cstdint>
#include <cstddef>

#define MAX_N 131072
#define MAX_E 2000000
#define OUTF 64
#define INF 128
#define NPB 64   // nodes per gemm block

// Scratch (allocation-free rule: __device__ globals).
__device__ __align__(16) __half g_msg_h[(size_t)MAX_N * OUTF];   // fp16 messages
__device__ __align__(16) float g_alpha_src[MAX_N];
__device__ __align__(16) float g_alpha_dst[MAX_N];
__device__ __align__(16) float2 g_sorted[MAX_E];   // (w, s-bits) in dst-sorted order
__device__ __align__(16) int g_hist[MAX_N];
__device__ __align__(16) int g_start[MAX_N];
__device__ __align__(16) int g_cursor[MAX_N];
__device__ __align__(16) int g_bsum[512];

static __device__ __forceinline__ unsigned h2_bits(__half2 h) {
    return *reinterpret_cast<unsigned*>(&h);
}

// ---------------------------------------------------------------------------
// messages = x @ W^T (fp16 out) + per-node attention scalars. Zeroes g_hist.
// ---------------------------------------------------------------------------
__global__ __launch_bounds__(256) void gemm_kernel(
    const float* __restrict__ x, const float* __restrict__ W,
    const float* __restrict__ a, int N) {
    __shared__ __align__(16) float Ws[INF][OUTF];   // Ws[k][c] = W[c][k]
    __shared__ __align__(16) float Xs[NPB][33];
    __shared__ float As[2 * OUTF];
    __shared__ float Pd[8][NPB];
    __shared__ float Ps[8][NPB];

    int tid = threadIdx.x;
    int tx = tid >> 5;
    int ty = tid & 31;
    int nodeBase = blockIdx.x * NPB;

    if (tid < NPB) {
        int n = nodeBase + tid;
        if (n < N) g_hist[n] = 0;
    }

    for (int i = tid; i < OUTF * INF; i += 256) {
        int c = i >> 7;
        int k = i & 127;
        Ws[k][c] = W[i];
    }
    if (tid < 2 * OUTF) As[tid] = a[tid];

    float acc0[8], acc1[8];
#pragma unroll
    for (int j = 0; j < 8; j++) { acc0[j] = 0.f; acc1[j] = 0.f; }

    int n0 = nodeBase + ty * 2;
    int n1 = n0 + 1;

    for (int k0 = 0; k0 < INF; k0 += 32) {
        __syncthreads();
        for (int i = tid; i < NPB * 32; i += 256) {
            int n = i >> 5, kk = i & 31;
            int gn = min(nodeBase + n, N - 1);
            Xs[n][kk] = x[(size_t)gn * INF + k0 + kk];
        }
        __syncthreads();
#pragma unroll
        for (int kk = 0; kk < 32; kk++) {
            float4 wa = *reinterpret_cast<const float4*>(&Ws[k0 + kk][tx * 8]);
            float4 wb = *reinterpret_cast<const float4*>(&Ws[k0 + kk][tx * 8 + 4]);
            float xv0 = Xs[ty * 2][kk];
            float xv1 = Xs[ty * 2 + 1][kk];
            acc0[0] += xv0 * wa.x; acc0[1] += xv0 * wa.y;
            acc0[2] += xv0 * wa.z; acc0[3] += xv0 * wa.w;
            acc0[4] += xv0 * wb.x; acc0[5] += xv0 * wb.y;
            acc0[6] += xv0 * wb.z; acc0[7] += xv0 * wb.w;
            acc1[0] += xv1 * wa.x; acc1[1] += xv1 * wa.y;
            acc1[2] += xv1 * wa.z; acc1[3] += xv1 * wa.w;
            acc1[4] += xv1 * wb.x; acc1[5] += xv1 * wb.y;
            acc1[6] += xv1 * wb.z; acc1[7] += xv1 * wb.w;
        }
    }

    float pd0 = 0.f, ps0 = 0.f, pd1 = 0.f, ps1 = 0.f;
#pragma unroll
    for (int j = 0; j < 8; j++) {
        float ad = As[tx * 8 + j];
        float as = As[OUTF + tx * 8 + j];
        pd0 += acc0[j] * ad; ps0 += acc0[j] * as;
        pd1 += acc1[j] * ad; ps1 += acc1[j] * as;
    }
    Pd[tx][ty * 2] = pd0;     Ps[tx][ty * 2] = ps0;
    Pd[tx][ty * 2 + 1] = pd1; Ps[tx][ty * 2 + 1] = ps1;

    if (n0 < N) {
        uint4 v = make_uint4(h2_bits(__floats2half2_rn(acc0[0], acc0[1])),
                             h2_bits(__floats2half2_rn(acc0[2], acc0[3])),
                             h2_bits(__floats2half2_rn(acc0[4], acc0[5])),
                             h2_bits(__floats2half2_rn(acc0[6], acc0[7])));
        *reinterpret_cast<uint4*>(g_msg_h + (size_t)n0 * OUTF + tx * 8) = v;
    }
    if (n1 < N) {
        uint4 v = make_uint4(h2_bits(__floats2half2_rn(acc1[0], acc1[1])),
                             h2_bits(__floats2half2_rn(acc1[2], acc1[3])),
                             h2_bits(__floats2half2_rn(acc1[4], acc1[5])),
                             h2_bits(__floats2half2_rn(acc1[6], acc1[7])));
        *reinterpret_cast<uint4*>(g_msg_h + (size_t)n1 * OUTF + tx * 8) = v;
    }

    __syncthreads();
    if (tid < NPB) {
        float sd = 0.f, ss = 0.f;
#pragma unroll
        for (int wg = 0; wg < 8; wg++) { sd += Pd[wg][tid]; ss += Ps[wg][tid]; }
        int n = nodeBase + tid;
        if (n < N) { g_alpha_dst[n] = sd; g_alpha_src[n] = ss; }
    }
}

// ---------------------------------------------------------------------------
// Histogram of dst only (reads just the second half of edge_index).
// ---------------------------------------------------------------------------
__global__ void hist_kernel(const void* __restrict__ ei_raw, long long E) {
    const int* ei32 = (const int*)ei_raw;
    bool is64 = (ei32[1] == 0) & (ei32[3] == 0) & (ei32[5] == 0) & (ei32[7] == 0);

    long long i = (long long)blockIdx.x * blockDim.x + threadIdx.x;
    if (i >= E || i >= MAX_E) return;
    int d;
    if (is64) d = (int)__ldg(((const long long*)ei_raw) + E + i);
    else      d = __ldg(ei32 + E + i);
    atomicAdd(&g_hist[d], 1);
}

// ---------------------------------------------------------------------------
// Exclusive scan of g_hist -> g_start (3 kernels; N <= 131072 -> <=128 blocks)
// ---------------------------------------------------------------------------
__global__ __launch_bounds__(256) void scan1_kernel(int N) {
    __shared__ int sh[256];
    int tid = threadIdx.x;
    int base = blockIdx.x * 1024 + tid * 4;
    int v0 = (base + 0 < N) ? g_hist[base + 0] : 0;
    int v1 = (base + 1 < N) ? g_hist[base + 1] : 0;
    int v2 = (base + 2 < N) ? g_hist[base + 2] : 0;
    int v3 = (base + 3 < N) ? g_hist[base + 3] : 0;
    int t = v0 + v1 + v2 + v3;
    sh[tid] = t;
    __syncthreads();
    for (int off = 1; off < 256; off <<= 1) {
        int x = 0;
        if (tid >= off) x = sh[tid - off];
        __syncthreads();
        if (tid >= off) sh[tid] += x;
        __syncthreads();
    }
    int run = sh[tid] - t;   // exclusive prefix of this thread's chunk
    if (base + 0 < N) g_start[base + 0] = run; run += v0;
    if (base + 1 < N) g_start[base + 1] = run; run += v1;
    if (base + 2 < N) g_start[base + 2] = run; run += v2;
    if (base + 3 < N) g_start[base + 3] = run;
    if (tid == 255) g_bsum[blockIdx.x] = sh[255];
}

// Parallel exclusive scan of up to 512 block sums (one 512-thread block).
__global__ __launch_bounds__(512) void scan2_kernel(int nblk) {
    __shared__ int sh[512];
    int tid = threadIdx.x;
    int v = (tid < nblk) ? g_bsum[tid] : 0;
    sh[tid] = v;
    __syncthreads();
    for (int off = 1; off < 512; off <<= 1) {
        int x = 0;
        if (tid >= off) x = sh[tid - off];
        __syncthreads();
        if (tid >= off) sh[tid] += x;
        __syncthreads();
    }
    if (tid < nblk) g_bsum[tid] = sh[tid] - v;   // exclusive
}

__global__ void scan3_kernel(int N) {
    int i = blockIdx.x * blockDim.x + threadIdx.x;
    if (i < N) {
        int v = g_start[i] + g_bsum[i >> 10];
        g_start[i] = v;
        g_cursor[i] = v;
    }
}

// ---------------------------------------------------------------------------
// Weight + place: compute w per edge, write (w, s-bits) record directly into
// dst-sorted position via ticket atomic. No staging arrays.
// ---------------------------------------------------------------------------
__global__ void weight_place_kernel(const void* __restrict__ ei_raw, long long E) {
    const int* ei32 = (const int*)ei_raw;
    bool is64 = (ei32[1] == 0) & (ei32[3] == 0) & (ei32[5] == 0) & (ei32[7] == 0);

    long long i = (long long)blockIdx.x * blockDim.x + threadIdx.x;
    if (i >= E || i >= MAX_E) return;
    int s, d;
    if (is64) {
        const long long* e64 = (const long long*)ei_raw;
        s = (int)__ldg(e64 + i);
        d = (int)__ldg(e64 + E + i);
    } else {
        s = __ldg(ei32 + i);
        d = __ldg(ei32 + E + i);
    }
    float e = g_alpha_dst[d] + g_alpha_src[s];
    e = (e >= 0.f) ? e : 0.01f * e;
    float w = __expf(e);
    int pos = atomicAdd(&g_cursor[d], 1);
    g_sorted[pos] = make_float2(w, __int_as_float(s));
}

// ---------------------------------------------------------------------------
// Aggregate: one warp per dst, 2 records per iteration (2 gathers in flight).
// Lane covers 2 output cols. Denominator identical across lanes (no reduce).
// Folds self-loop + normalize; single write of out.
// ---------------------------------------------------------------------------
__global__ __launch_bounds__(256) void aggregate_kernel(float* __restrict__ out, int N) {
    int gw = (blockIdx.x * blockDim.x + threadIdx.x) >> 5;
    int lane = threadIdx.x & 31;
    if (gw >= N) return;
    int d = gw;
    int start = __ldg(&g_start[d]);
    int end = __ldg(&g_cursor[d]);

    float accx = 0.f, accy = 0.f, denom = 0.f;
    int e = start;
    for (; e + 2 <= end; e += 2) {
        float2 r0 = __ldg(&g_sorted[e]);
        float2 r1 = __ldg(&g_sorted[e + 1]);
        int s0 = __float_as_int(r0.y);
        int s1 = __float_as_int(r1.y);
        __half2 h0 = __ldg(reinterpret_cast<const __half2*>(
            g_msg_h + (size_t)s0 * OUTF) + lane);
        __half2 h1 = __ldg(reinterpret_cast<const __half2*>(
            g_msg_h + (size_t)s1 * OUTF) + lane);
        float2 f0 = __half22float2(h0);
        float2 f1 = __half22float2(h1);
        accx += r0.x * f0.x + r1.x * f1.x;
        accy += r0.x * f0.y + r1.x * f1.y;
        denom += r0.x + r1.x;
    }
    if (e < end) {
        float2 r = __ldg(&g_sorted[e]);
        int s = __float_as_int(r.y);
        __half2 h = __ldg(reinterpret_cast<const __half2*>(
            g_msg_h + (size_t)s * OUTF) + lane);
        float2 f = __half22float2(h);
        accx += r.x * f.x;
        accy += r.x * f.y;
        denom += r.x;
    }

    // self-loop
    float e0 = g_alpha_dst[d] + g_alpha_src[d];
    e0 = (e0 >= 0.f) ? e0 : 0.01f * e0;
    float ws = __expf(e0);
    __half2 hm = __ldg(reinterpret_cast<const __half2*>(
        g_msg_h + (size_t)d * OUTF) + lane);
    float2 fm = __half22float2(hm);
    accx += ws * fm.x;
    accy += ws * fm.y;
    denom += ws;

    float inv = 1.0f / fmaxf(denom, 1e-6f);
    reinterpret_cast<float2*>(out + (size_t)d * OUTF)[lane] =
        make_float2(accx * inv, accy * inv);
}

extern "C" void kernel_launch(void* const* d_in, const int* in_sizes, int n_in,
                              void* d_out, int out_size) {
    // Identify inputs BY SIZE:
    //   a -> 128, W -> 8192, x -> N*128 (== 2*out_size), edge_index -> rest
    const float* x = nullptr;
    const float* W = nullptr;
    const float* a = nullptr;
    const void* ei = nullptr;
    long long ei_elems = 0;

    int N = out_size / OUTF;
    long long x_elems = (long long)N * INF;

    for (int i = 0; i < n_in; i++) {
        long long sz = in_sizes[i];
        if (sz == 2 * OUTF) {
            a = (const float*)d_in[i];
        } else if (sz == (long long)OUTF * INF) {
            W = (const float*)d_in[i];
        } else if (sz == x_elems) {
            x = (const float*)d_in[i];
        } else {
            ei = d_in[i];
            ei_elems = sz;
        }
    }
    float* out = (float*)d_out;
    long long E = ei_elems / 2;
    if (E > MAX_E) E = MAX_E;

    gemm_kernel<<<(N + NPB - 1) / NPB, 256>>>(x, W, a, N);

    hist_kernel<<<(unsigned int)((E + 255) / 256), 256>>>(ei, E);

    int nblk = (N + 1023) / 1024;
    scan1_kernel<<<nblk, 256>>>(N);
    scan2_kernel<<<1, 512>>>(nblk);
    scan3_kernel<<<(N + 255) / 256, 256>>>(N);

    weight_place_kernel<<<(unsigned int)((E + 255) / 256), 256>>>(ei, E);

    aggregate_kernel<<<(N * 32 + 255) / 256, 256>>>(out, N);
}

// round 11
// speedup vs baseline: 1.9861x; 1.4145x over previous
#include <cuda_runtime.h>
#include <cuda_fp16.h>
#include <cstdint>
#include <cstddef>

#define MAX_N 131072
#define MAX_E 2000000
#define OUTF 64
#define INF 128
#define BLK_M 128   // nodes per gemm block
#define KSTG 32     // K per stage

// Scratch (allocation-free rule: __device__ globals).
__device__ __align__(16) __half g_msg_h[(size_t)MAX_N * OUTF];   // fp16 messages
__device__ __align__(16) float g_alpha_src[MAX_N];
__device__ __align__(16) float g_alpha_dst[MAX_N];
__device__ __align__(16) float2 g_sorted[MAX_E];   // (w, s-bits) dst-sorted
__device__ __align__(16) int g_hist[MAX_N];        // zeroed by scan1 after use
__device__ __align__(16) int g_start[MAX_N];
__device__ __align__(16) int g_cursor[MAX_N];
__device__ __align__(16) int g_bsum[512];

static __device__ __forceinline__ unsigned h2_bits(__half2 h) {
    return *reinterpret_cast<unsigned*>(&h);
}
static __device__ __forceinline__ uint32_t f2tf32(float f) {
    uint32_t u;
    asm("cvt.rna.tf32.f32 %0, %1;" : "=r"(u) : "f"(f));
    return u;
}
static __device__ __forceinline__ void mma_tf32(
    float& c0, float& c1, float& c2, float& c3,
    uint32_t a0, uint32_t a1, uint32_t a2, uint32_t a3,
    uint32_t b0, uint32_t b1) {
    asm volatile(
        "mma.sync.aligned.m16n8k8.row.col.f32.tf32.tf32.f32 "
        "{%0,%1,%2,%3}, {%4,%5,%6,%7}, {%8,%9}, {%0,%1,%2,%3};"
        : "+f"(c0), "+f"(c1), "+f"(c2), "+f"(c3)
        : "r"(a0), "r"(a1), "r"(a2), "r"(a3), "r"(b0), "r"(b1));
}

// ---------------------------------------------------------------------------
// Fused: dst histogram (slice) + messages = x@W^T via tf32 mma (fp16 out)
//        + EXACT fp32 alpha (v = W^T a computed fp32 from smem; alpha = x.v).
// Block: 256 threads (8 warps); tile 128 nodes x 64 cols; K staged 4 x 32.
// Warp w computes rows [16w,16w+16); m16n8k8: 8 n-tiles x 4 k-steps/stage.
// ---------------------------------------------------------------------------
__global__ __launch_bounds__(256) void gemm_mma_kernel(
    const float* __restrict__ x, const float* __restrict__ W,
    const float* __restrict__ a, int N,
    const void* __restrict__ ei_raw, long long E, int epb) {
    __shared__ __align__(16) float As[BLK_M][KSTG + 4];   // pitch 36: frag + f4 conflict-free
    __shared__ __align__(16) float Bs[OUTF][KSTG + 4];    // Bs[n][k] = W[n][k0+k]
    __shared__ __align__(16) float Avec[2 * OUTF];
    __shared__ __align__(16) float Vd[KSTG], Vs[KSTG];

    int tid = threadIdx.x;
    int warp = tid >> 5;
    int lane = tid & 31;
    int gid = lane >> 2;      // groupID 0..7
    int tig = lane & 3;       // thread-in-group 0..3
    int nodeBase = blockIdx.x * BLK_M;

    // ---- fused dst histogram over this block's edge slice ----
    {
        const int* ei32 = (const int*)ei_raw;
        bool is64 = (ei32[1] == 0) & (ei32[3] == 0) & (ei32[5] == 0) & (ei32[7] == 0);
        long long e0 = (long long)blockIdx.x * epb;
        long long e1 = e0 + epb; if (e1 > E) e1 = E;
        for (long long i = e0 + tid; i < e1; i += 256) {
            int d = is64 ? (int)__ldg(((const long long*)ei_raw) + E + i)
                         : __ldg(((const int*)ei_raw) + E + i);
            atomicAdd(&g_hist[d], 1);
        }
    }

    if (tid < 2 * OUTF) Avec[tid] = a[tid];

    float c[8][4];
#pragma unroll
    for (int nt = 0; nt < 8; nt++)
#pragma unroll
        for (int j = 0; j < 4; j++) c[nt][j] = 0.f;

    float alpha_d = 0.f, alpha_s = 0.f;   // valid for tid < 128 (node = nodeBase+tid)

    for (int s = 0; s < 4; s++) {
        int k0 = s * KSTG;
        __syncthreads();   // previous stage fully consumed
        // stage As (128 x 32 fp32, coalesced)
        for (int i = tid; i < BLK_M * KSTG; i += 256) {
            int r = i >> 5, k = i & 31;
            int gn = nodeBase + r; if (gn > N - 1) gn = N - 1;
            As[r][k] = x[(size_t)gn * INF + k0 + k];
        }
        // stage Bs (64 x 32 fp32)
        for (int i = tid; i < OUTF * KSTG; i += 256) {
            int n = i >> 5, k = i & 31;
            Bs[n][k] = W[n * INF + k0 + k];
        }
        __syncthreads();
        // exact fp32 v for this stage: Vd[k] = sum_n Bs[n][k]*a[n]; Vs with a[64+n]
        if (tid < 64) {
            int k = tid & 31;
            bool dsel = tid < 32;
            float v = 0.f;
            const float* av = dsel ? Avec : (Avec + OUTF);
#pragma unroll 8
            for (int n = 0; n < OUTF; n++) v += Bs[n][k] * av[n];
            if (dsel) Vd[k] = v; else Vs[k] = v;
        }
        __syncthreads();
        // mma: 4 k-steps x 8 n-tiles
        int rbase = warp * 16;
#pragma unroll
        for (int ks = 0; ks < 4; ks++) {
            int kk = ks * 8;
            uint32_t A0 = f2tf32(As[rbase + gid][kk + tig]);
            uint32_t A1 = f2tf32(As[rbase + gid + 8][kk + tig]);
            uint32_t A2 = f2tf32(As[rbase + gid][kk + tig + 4]);
            uint32_t A3 = f2tf32(As[rbase + gid + 8][kk + tig + 4]);
#pragma unroll
            for (int nt = 0; nt < 8; nt++) {
                uint32_t B0 = f2tf32(Bs[nt * 8 + gid][kk + tig]);
                uint32_t B1 = f2tf32(Bs[nt * 8 + gid][kk + tig + 4]);
                mma_tf32(c[nt][0], c[nt][1], c[nt][2], c[nt][3],
                         A0, A1, A2, A3, B0, B1);
            }
        }
        // exact fp32 alpha partial from staged x (tid<128: one node each)
        if (tid < 128) {
            const float4* xr = reinterpret_cast<const float4*>(&As[tid][0]);
#pragma unroll
            for (int q = 0; q < KSTG / 4; q++) {
                float4 xv = xr[q];
                alpha_d += xv.x * Vd[4 * q] + xv.y * Vd[4 * q + 1]
                         + xv.z * Vd[4 * q + 2] + xv.w * Vd[4 * q + 3];
                alpha_s += xv.x * Vs[4 * q] + xv.y * Vs[4 * q + 1]
                         + xv.z * Vs[4 * q + 2] + xv.w * Vs[4 * q + 3];
            }
        }
    }

    // epilogue: fp16 messages
    int r0 = warp * 16 + gid;
    int cbase = 2 * tig;
#pragma unroll
    for (int nt = 0; nt < 8; nt++) {
        int col = nt * 8 + cbase;
        if (nodeBase + r0 < N) {
            __half2 h = __floats2half2_rn(c[nt][0], c[nt][1]);
            *reinterpret_cast<unsigned*>(
                g_msg_h + (size_t)(nodeBase + r0) * OUTF + col) = h2_bits(h);
        }
        if (nodeBase + r0 + 8 < N) {
            __half2 h = __floats2half2_rn(c[nt][2], c[nt][3]);
            *reinterpret_cast<unsigned*>(
                g_msg_h + (size_t)(nodeBase + r0 + 8) * OUTF + col) = h2_bits(h);
        }
    }
    if (tid < 128 && nodeBase + tid < N) {
        g_alpha_dst[nodeBase + tid] = alpha_d;
        g_alpha_src[nodeBase + tid] = alpha_s;
    }
}

// ---------------------------------------------------------------------------
// Exclusive scan of g_hist -> g_start; scan1 also re-zeroes g_hist for the
// next graph replay (initial zero comes from BSS init; capture doesn't run).
// ---------------------------------------------------------------------------
__global__ __launch_bounds__(256) void scan1_kernel(int N) {
    __shared__ int sh[256];
    int tid = threadIdx.x;
    int base = blockIdx.x * 1024 + tid * 4;
    int v0 = (base + 0 < N) ? g_hist[base + 0] : 0;
    int v1 = (base + 1 < N) ? g_hist[base + 1] : 0;
    int v2 = (base + 2 < N) ? g_hist[base + 2] : 0;
    int v3 = (base + 3 < N) ? g_hist[base + 3] : 0;
    if (base + 0 < N) g_hist[base + 0] = 0;
    if (base + 1 < N) g_hist[base + 1] = 0;
    if (base + 2 < N) g_hist[base + 2] = 0;
    if (base + 3 < N) g_hist[base + 3] = 0;
    int t = v0 + v1 + v2 + v3;
    sh[tid] = t;
    __syncthreads();
    for (int off = 1; off < 256; off <<= 1) {
        int x = 0;
        if (tid >= off) x = sh[tid - off];
        __syncthreads();
        if (tid >= off) sh[tid] += x;
        __syncthreads();
    }
    int run = sh[tid] - t;
    if (base + 0 < N) g_start[base + 0] = run; run += v0;
    if (base + 1 < N) g_start[base + 1] = run; run += v1;
    if (base + 2 < N) g_start[base + 2] = run; run += v2;
    if (base + 3 < N) g_start[base + 3] = run;
    if (tid == 255) g_bsum[blockIdx.x] = sh[255];
}

__global__ __launch_bounds__(512) void scan2_kernel(int nblk) {
    __shared__ int sh[512];
    int tid = threadIdx.x;
    int v = (tid < nblk) ? g_bsum[tid] : 0;
    sh[tid] = v;
    __syncthreads();
    for (int off = 1; off < 512; off <<= 1) {
        int x = 0;
        if (tid >= off) x = sh[tid - off];
        __syncthreads();
        if (tid >= off) sh[tid] += x;
        __syncthreads();
    }
    if (tid < nblk) g_bsum[tid] = sh[tid] - v;   // exclusive
}

__global__ void scan3_kernel(int N) {
    int i = blockIdx.x * blockDim.x + threadIdx.x;
    if (i < N) {
        int v = g_start[i] + g_bsum[i >> 10];
        g_start[i] = v;
        g_cursor[i] = v;
    }
}

// ---------------------------------------------------------------------------
// Weight + place: w per edge, record (w, s-bits) straight into sorted position.
// ---------------------------------------------------------------------------
__global__ void weight_place_kernel(const void* __restrict__ ei_raw, long long E) {
    const int* ei32 = (const int*)ei_raw;
    bool is64 = (ei32[1] == 0) & (ei32[3] == 0) & (ei32[5] == 0) & (ei32[7] == 0);

    long long i = (long long)blockIdx.x * blockDim.x + threadIdx.x;
    if (i >= E || i >= MAX_E) return;
    int s, d;
    if (is64) {
        const long long* e64 = (const long long*)ei_raw;
        s = (int)__ldg(e64 + i);
        d = (int)__ldg(e64 + E + i);
    } else {
        s = __ldg(ei32 + i);
        d = __ldg(ei32 + E + i);
    }
    float e = g_alpha_dst[d] + g_alpha_src[s];
    e = (e >= 0.f) ? e : 0.01f * e;
    float w = __expf(e);
    int pos = atomicAdd(&g_cursor[d], 1);
    g_sorted[pos] = make_float2(w, __int_as_float(s));
}

// ---------------------------------------------------------------------------
// Aggregate: one warp per dst, 2 records/iter (2 gathers in flight).
// Lane covers 2 output cols; denom identical across lanes (no reduce).
// Folds self-loop + normalization; writes out once.
// ---------------------------------------------------------------------------
__global__ __launch_bounds__(256) void aggregate_kernel(float* __restrict__ out, int N) {
    int gw = (blockIdx.x * blockDim.x + threadIdx.x) >> 5;
    int lane = threadIdx.x & 31;
    if (gw >= N) return;
    int d = gw;
    int start = __ldg(&g_start[d]);
    int end = __ldg(&g_cursor[d]);

    float accx = 0.f, accy = 0.f, denom = 0.f;
    int e = start;
    for (; e + 2 <= end; e += 2) {
        float2 r0 = __ldg(&g_sorted[e]);
        float2 r1 = __ldg(&g_sorted[e + 1]);
        int s0 = __float_as_int(r0.y);
        int s1 = __float_as_int(r1.y);
        __half2 h0 = __ldg(reinterpret_cast<const __half2*>(
            g_msg_h + (size_t)s0 * OUTF) + lane);
        __half2 h1 = __ldg(reinterpret_cast<const __half2*>(
            g_msg_h + (size_t)s1 * OUTF) + lane);
        float2 f0 = __half22float2(h0);
        float2 f1 = __half22float2(h1);
        accx += r0.x * f0.x + r1.x * f1.x;
        accy += r0.x * f0.y + r1.x * f1.y;
        denom += r0.x + r1.x;
    }
    if (e < end) {
        float2 r = __ldg(&g_sorted[e]);
        int s = __float_as_int(r.y);
        __half2 h = __ldg(reinterpret_cast<const __half2*>(
            g_msg_h + (size_t)s * OUTF) + lane);
        float2 f = __half22float2(h);
        accx += r.x * f.x;
        accy += r.x * f.y;
        denom += r.x;
    }

    // self-loop
    float e0 = g_alpha_dst[d] + g_alpha_src[d];
    e0 = (e0 >= 0.f) ? e0 : 0.01f * e0;
    float ws = __expf(e0);
    __half2 hm = __ldg(reinterpret_cast<const __half2*>(
        g_msg_h + (size_t)d * OUTF) + lane);
    float2 fm = __half22float2(hm);
    accx += ws * fm.x;
    accy += ws * fm.y;
    denom += ws;

    float inv = 1.0f / fmaxf(denom, 1e-6f);
    reinterpret_cast<float2*>(out + (size_t)d * OUTF)[lane] =
        make_float2(accx * inv, accy * inv);
}

extern "C" void kernel_launch(void* const* d_in, const int* in_sizes, int n_in,
                              void* d_out, int out_size) {
    // Identify inputs BY SIZE:
    //   a -> 128, W -> 8192, x -> N*128 (== 2*out_size), edge_index -> rest
    const float* x = nullptr;
    const float* W = nullptr;
    const float* a = nullptr;
    const void* ei = nullptr;
    long long ei_elems = 0;

    int N = out_size / OUTF;
    long long x_elems = (long long)N * INF;

    for (int i = 0; i < n_in; i++) {
        long long sz = in_sizes[i];
        if (sz == 2 * OUTF) {
            a = (const float*)d_in[i];
        } else if (sz == (long long)OUTF * INF) {
            W = (const float*)d_in[i];
        } else if (sz == x_elems) {
            x = (const float*)d_in[i];
        } else {
            ei = d_in[i];
            ei_elems = sz;
        }
    }
    float* out = (float*)d_out;
    long long E = ei_elems / 2;
    if (E > MAX_E) E = MAX_E;

    int grid = (N + BLK_M - 1) / BLK_M;
    int epb = (int)((E + grid - 1) / grid);
    gemm_mma_kernel<<<grid, 256>>>(x, W, a, N, ei, E, epb);

    int nblk = (N + 1023) / 1024;
    scan1_kernel<<<nblk, 256>>>(N);
    scan2_kernel<<<1, 512>>>(nblk);
    scan3_kernel<<<(N + 255) / 256, 256>>>(N);

    weight_place_kernel<<<(unsigned int)((E + 255) / 256), 256>>>(ei, E);

    aggregate_kernel<<<(N * 32 + 255) / 256, 256>>>(out, N);
}

// round 12
// speedup vs baseline: 1.9998x; 1.0069x over previous
#include <cuda_runtime.h>
#include <cuda_fp16.h>
#include <cstdint>
#include <cstddef>

#define MAX_N 131072
#define MAX_E 2000000
#define OUTF 64
#define INF 128
#define BLK_M 128   // nodes per gemm block
#define KSTG 32     // K per stage

// Scratch (allocation-free rule: __device__ globals).
__device__ __align__(16) __half g_msg_h[(size_t)MAX_N * OUTF];   // fp16 messages
__device__ __align__(16) float g_alpha_src[MAX_N];
__device__ __align__(16) float g_alpha_dst[MAX_N];
__device__ __align__(16) float2 g_sorted[MAX_E];   // (w, s-bits) dst-sorted
__device__ __align__(16) int g_hist[MAX_N];        // zeroed by scan1 after use
__device__ __align__(16) int g_start[MAX_N];
__device__ __align__(16) int g_cursor[MAX_N];
__device__ __align__(16) int g_bsum[512];

static __device__ __forceinline__ unsigned h2_bits(__half2 h) {
    return *reinterpret_cast<unsigned*>(&h);
}
static __device__ __forceinline__ uint32_t f2tf32(float f) {
    uint32_t u;
    asm("cvt.rna.tf32.f32 %0, %1;" : "=r"(u) : "f"(f));
    return u;
}
static __device__ __forceinline__ void mma_tf32(
    float& c0, float& c1, float& c2, float& c3,
    uint32_t a0, uint32_t a1, uint32_t a2, uint32_t a3,
    uint32_t b0, uint32_t b1) {
    asm volatile(
        "mma.sync.aligned.m16n8k8.row.col.f32.tf32.tf32.f32 "
        "{%0,%1,%2,%3}, {%4,%5,%6,%7}, {%8,%9}, {%0,%1,%2,%3};"
        : "+f"(c0), "+f"(c1), "+f"(c2), "+f"(c3)
        : "r"(a0), "r"(a1), "r"(a2), "r"(a3), "r"(b0), "r"(b1));
}

// ---------------------------------------------------------------------------
// Fused: dst histogram (slice) + messages = x@W^T via tf32 mma (fp16 out)
//        + EXACT fp32 alpha (v = W^T a computed fp32 from smem; alpha = x.v).
// Block: 256 threads (8 warps); tile 128 nodes x 64 cols; K staged 4 x 32.
// ---------------------------------------------------------------------------
__global__ __launch_bounds__(256) void gemm_mma_kernel(
    const float* __restrict__ x, const float* __restrict__ W,
    const float* __restrict__ a, int N,
    const void* __restrict__ ei_raw, long long E, int epb) {
    __shared__ __align__(16) float As[BLK_M][KSTG + 4];
    __shared__ __align__(16) float Bs[OUTF][KSTG + 4];
    __shared__ __align__(16) float Avec[2 * OUTF];
    __shared__ __align__(16) float Vd[KSTG], Vs[KSTG];

    int tid = threadIdx.x;
    int warp = tid >> 5;
    int lane = tid & 31;
    int gid = lane >> 2;
    int tig = lane & 3;
    int nodeBase = blockIdx.x * BLK_M;

    // ---- fused dst histogram over this block's edge slice ----
    {
        const int* ei32 = (const int*)ei_raw;
        bool is64 = (ei32[1] == 0) & (ei32[3] == 0) & (ei32[5] == 0) & (ei32[7] == 0);
        long long e0 = (long long)blockIdx.x * epb;
        long long e1 = e0 + epb; if (e1 > E) e1 = E;
        for (long long i = e0 + tid; i < e1; i += 256) {
            int d = is64 ? (int)__ldg(((const long long*)ei_raw) + E + i)
                         : __ldg(((const int*)ei_raw) + E + i);
            atomicAdd(&g_hist[d], 1);
        }
    }

    if (tid < 2 * OUTF) Avec[tid] = a[tid];

    float c[8][4];
#pragma unroll
    for (int nt = 0; nt < 8; nt++)
#pragma unroll
        for (int j = 0; j < 4; j++) c[nt][j] = 0.f;

    float alpha_d = 0.f, alpha_s = 0.f;

    for (int s = 0; s < 4; s++) {
        int k0 = s * KSTG;
        __syncthreads();
        for (int i = tid; i < BLK_M * KSTG; i += 256) {
            int r = i >> 5, k = i & 31;
            int gn = nodeBase + r; if (gn > N - 1) gn = N - 1;
            As[r][k] = x[(size_t)gn * INF + k0 + k];
        }
        for (int i = tid; i < OUTF * KSTG; i += 256) {
            int n = i >> 5, k = i & 31;
            Bs[n][k] = W[n * INF + k0 + k];
        }
        __syncthreads();
        if (tid < 64) {
            int k = tid & 31;
            bool dsel = tid < 32;
            float v = 0.f;
            const float* av = dsel ? Avec : (Avec + OUTF);
#pragma unroll 8
            for (int n = 0; n < OUTF; n++) v += Bs[n][k] * av[n];
            if (dsel) Vd[k] = v; else Vs[k] = v;
        }
        __syncthreads();
        int rbase = warp * 16;
#pragma unroll
        for (int ks = 0; ks < 4; ks++) {
            int kk = ks * 8;
            uint32_t A0 = f2tf32(As[rbase + gid][kk + tig]);
            uint32_t A1 = f2tf32(As[rbase + gid + 8][kk + tig]);
            uint32_t A2 = f2tf32(As[rbase + gid][kk + tig + 4]);
            uint32_t A3 = f2tf32(As[rbase + gid + 8][kk + tig + 4]);
#pragma unroll
            for (int nt = 0; nt < 8; nt++) {
                uint32_t B0 = f2tf32(Bs[nt * 8 + gid][kk + tig]);
                uint32_t B1 = f2tf32(Bs[nt * 8 + gid][kk + tig + 4]);
                mma_tf32(c[nt][0], c[nt][1], c[nt][2], c[nt][3],
                         A0, A1, A2, A3, B0, B1);
            }
        }
        if (tid < 128) {
            const float4* xr = reinterpret_cast<const float4*>(&As[tid][0]);
#pragma unroll
            for (int q = 0; q < KSTG / 4; q++) {
                float4 xv = xr[q];
                alpha_d += xv.x * Vd[4 * q] + xv.y * Vd[4 * q + 1]
                         + xv.z * Vd[4 * q + 2] + xv.w * Vd[4 * q + 3];
                alpha_s += xv.x * Vs[4 * q] + xv.y * Vs[4 * q + 1]
                         + xv.z * Vs[4 * q + 2] + xv.w * Vs[4 * q + 3];
            }
        }
    }

    int r0 = warp * 16 + gid;
    int cbase = 2 * tig;
#pragma unroll
    for (int nt = 0; nt < 8; nt++) {
        int col = nt * 8 + cbase;
        if (nodeBase + r0 < N) {
            __half2 h = __floats2half2_rn(c[nt][0], c[nt][1]);
            *reinterpret_cast<unsigned*>(
                g_msg_h + (size_t)(nodeBase + r0) * OUTF + col) = h2_bits(h);
        }
        if (nodeBase + r0 + 8 < N) {
            __half2 h = __floats2half2_rn(c[nt][2], c[nt][3]);
            *reinterpret_cast<unsigned*>(
                g_msg_h + (size_t)(nodeBase + r0 + 8) * OUTF + col) = h2_bits(h);
        }
    }
    if (tid < 128 && nodeBase + tid < N) {
        g_alpha_dst[nodeBase + tid] = alpha_d;
        g_alpha_src[nodeBase + tid] = alpha_s;
    }
}

// ---------------------------------------------------------------------------
// Exclusive scan of g_hist -> g_start; scan1 re-zeroes g_hist for next replay.
// ---------------------------------------------------------------------------
__global__ __launch_bounds__(256) void scan1_kernel(int N) {
    __shared__ int sh[256];
    int tid = threadIdx.x;
    int base = blockIdx.x * 1024 + tid * 4;
    int v0 = (base + 0 < N) ? g_hist[base + 0] : 0;
    int v1 = (base + 1 < N) ? g_hist[base + 1] : 0;
    int v2 = (base + 2 < N) ? g_hist[base + 2] : 0;
    int v3 = (base + 3 < N) ? g_hist[base + 3] : 0;
    if (base + 0 < N) g_hist[base + 0] = 0;
    if (base + 1 < N) g_hist[base + 1] = 0;
    if (base + 2 < N) g_hist[base + 2] = 0;
    if (base + 3 < N) g_hist[base + 3] = 0;
    int t = v0 + v1 + v2 + v3;
    sh[tid] = t;
    __syncthreads();
    for (int off = 1; off < 256; off <<= 1) {
        int x = 0;
        if (tid >= off) x = sh[tid - off];
        __syncthreads();
        if (tid >= off) sh[tid] += x;
        __syncthreads();
    }
    int run = sh[tid] - t;
    if (base + 0 < N) g_start[base + 0] = run; run += v0;
    if (base + 1 < N) g_start[base + 1] = run; run += v1;
    if (base + 2 < N) g_start[base + 2] = run; run += v2;
    if (base + 3 < N) g_start[base + 3] = run;
    if (tid == 255) g_bsum[blockIdx.x] = sh[255];
}

__global__ __launch_bounds__(512) void scan2_kernel(int nblk) {
    __shared__ int sh[512];
    int tid = threadIdx.x;
    int v = (tid < nblk) ? g_bsum[tid] : 0;
    sh[tid] = v;
    __syncthreads();
    for (int off = 1; off < 512; off <<= 1) {
        int x = 0;
        if (tid >= off) x = sh[tid - off];
        __syncthreads();
        if (tid >= off) sh[tid] += x;
        __syncthreads();
    }
    if (tid < nblk) g_bsum[tid] = sh[tid] - v;
}

__global__ void scan3_kernel(int N) {
    int i = blockIdx.x * blockDim.x + threadIdx.x;
    if (i < N) {
        int v = g_start[i] + g_bsum[i >> 10];
        g_start[i] = v;
        g_cursor[i] = v;
    }
}

// ---------------------------------------------------------------------------
// Weight + place: 2 edges per thread (range halves; both coalesced). Two
// independent alpha-gather chains + cursor atomics in flight.
// ---------------------------------------------------------------------------
__global__ void weight_place_kernel(const void* __restrict__ ei_raw, long long E) {
    const int* ei32 = (const int*)ei_raw;
    bool is64 = (ei32[1] == 0) & (ei32[3] == 0) & (ei32[5] == 0) & (ei32[7] == 0);

    long long half = (E + 1) / 2;
    long long i0 = (long long)blockIdx.x * blockDim.x + threadIdx.x;
    if (i0 >= half) return;
    long long i1 = i0 + half;
    bool v1 = i1 < E;

    int s0, d0, s1 = 0, d1 = 0;
    if (is64) {
        const long long* e64 = (const long long*)ei_raw;
        s0 = (int)__ldg(e64 + i0);
        d0 = (int)__ldg(e64 + E + i0);
        if (v1) { s1 = (int)__ldg(e64 + i1); d1 = (int)__ldg(e64 + E + i1); }
    } else {
        s0 = __ldg(ei32 + i0);
        d0 = __ldg(ei32 + E + i0);
        if (v1) { s1 = __ldg(ei32 + i1); d1 = __ldg(ei32 + E + i1); }
    }
    float ad0 = g_alpha_dst[d0], as0 = g_alpha_src[s0];
    float ad1 = 0.f, as1 = 0.f;
    if (v1) { ad1 = g_alpha_dst[d1]; as1 = g_alpha_src[s1]; }

    float e0 = ad0 + as0;
    e0 = (e0 >= 0.f) ? e0 : 0.01f * e0;
    float w0 = __expf(e0);
    int p0 = atomicAdd(&g_cursor[d0], 1);
    g_sorted[p0] = make_float2(w0, __int_as_float(s0));
    if (v1) {
        float e1 = ad1 + as1;
        e1 = (e1 >= 0.f) ? e1 : 0.01f * e1;
        float w1 = __expf(e1);
        int p1 = atomicAdd(&g_cursor[d1], 1);
        g_sorted[p1] = make_float2(w1, __int_as_float(s1));
    }
}

// ---------------------------------------------------------------------------
// Aggregate: one warp per dst, 4 records/iter (4 row-gathers in flight).
// Lane covers 2 output cols; denom identical across lanes (no reduce).
// Folds self-loop + normalization; writes out once.
// ---------------------------------------------------------------------------
__global__ __launch_bounds__(256) void aggregate_kernel(float* __restrict__ out, int N) {
    int gw = (blockIdx.x * blockDim.x + threadIdx.x) >> 5;
    int lane = threadIdx.x & 31;
    if (gw >= N) return;
    int d = gw;
    int start = __ldg(&g_start[d]);
    int end = __ldg(&g_cursor[d]);

    float accx = 0.f, accy = 0.f, denom = 0.f;
    int e = start;
    for (; e + 4 <= end; e += 4) {
        float2 r0 = __ldg(&g_sorted[e]);
        float2 r1 = __ldg(&g_sorted[e + 1]);
        float2 r2 = __ldg(&g_sorted[e + 2]);
        float2 r3 = __ldg(&g_sorted[e + 3]);
        __half2 h0 = __ldg(reinterpret_cast<const __half2*>(
            g_msg_h + (size_t)__float_as_int(r0.y) * OUTF) + lane);
        __half2 h1 = __ldg(reinterpret_cast<const __half2*>(
            g_msg_h + (size_t)__float_as_int(r1.y) * OUTF) + lane);
        __half2 h2 = __ldg(reinterpret_cast<const __half2*>(
            g_msg_h + (size_t)__float_as_int(r2.y) * OUTF) + lane);
        __half2 h3 = __ldg(reinterpret_cast<const __half2*>(
            g_msg_h + (size_t)__float_as_int(r3.y) * OUTF) + lane);
        float2 f0 = __half22float2(h0);
        float2 f1 = __half22float2(h1);
        float2 f2 = __half22float2(h2);
        float2 f3 = __half22float2(h3);
        accx += r0.x * f0.x + r1.x * f1.x + r2.x * f2.x + r3.x * f3.x;
        accy += r0.x * f0.y + r1.x * f1.y + r2.x * f2.y + r3.x * f3.y;
        denom += r0.x + r1.x + r2.x + r3.x;
    }
    if (e + 2 <= end) {
        float2 r0 = __ldg(&g_sorted[e]);
        float2 r1 = __ldg(&g_sorted[e + 1]);
        __half2 h0 = __ldg(reinterpret_cast<const __half2*>(
            g_msg_h + (size_t)__float_as_int(r0.y) * OUTF) + lane);
        __half2 h1 = __ldg(reinterpret_cast<const __half2*>(
            g_msg_h + (size_t)__float_as_int(r1.y) * OUTF) + lane);
        float2 f0 = __half22float2(h0);
        float2 f1 = __half22float2(h1);
        accx += r0.x * f0.x + r1.x * f1.x;
        accy += r0.x * f0.y + r1.x * f1.y;
        denom += r0.x + r1.x;
        e += 2;
    }
    if (e < end) {
        float2 r = __ldg(&g_sorted[e]);
        __half2 h = __ldg(reinterpret_cast<const __half2*>(
            g_msg_h + (size_t)__float_as_int(r.y) * OUTF) + lane);
        float2 f = __half22float2(h);
        accx += r.x * f.x;
        accy += r.x * f.y;
        denom += r.x;
    }

    // self-loop
    float e0 = g_alpha_dst[d] + g_alpha_src[d];
    e0 = (e0 >= 0.f) ? e0 : 0.01f * e0;
    float ws = __expf(e0);
    __half2 hm = __ldg(reinterpret_cast<const __half2*>(
        g_msg_h + (size_t)d * OUTF) + lane);
    float2 fm = __half22float2(hm);
    accx += ws * fm.x;
    accy += ws * fm.y;
    denom += ws;

    float inv = 1.0f / fmaxf(denom, 1e-6f);
    reinterpret_cast<float2*>(out + (size_t)d * OUTF)[lane] =
        make_float2(accx * inv, accy * inv);
}

extern "C" void kernel_launch(void* const* d_in, const int* in_sizes, int n_in,
                              void* d_out, int out_size) {
    // Identify inputs BY SIZE:
    //   a -> 128, W -> 8192, x -> N*128 (== 2*out_size), edge_index -> rest
    const float* x = nullptr;
    const float* W = nullptr;
    const float* a = nullptr;
    const void* ei = nullptr;
    long long ei_elems = 0;

    int N = out_size / OUTF;
    long long x_elems = (long long)N * INF;

    for (int i = 0; i < n_in; i++) {
        long long sz = in_sizes[i];
        if (sz == 2 * OUTF) {
            a = (const float*)d_in[i];
        } else if (sz == (long long)OUTF * INF) {
            W = (const float*)d_in[i];
        } else if (sz == x_elems) {
            x = (const float*)d_in[i];
        } else {
            ei = d_in[i];
            ei_elems = sz;
        }
    }
    float* out = (float*)d_out;
    long long E = ei_elems / 2;
    if (E > MAX_E) E = MAX_E;

    int grid = (N + BLK_M - 1) / BLK_M;
    int epb = (int)((E + grid - 1) / grid);
    gemm_mma_kernel<<<grid, 256>>>(x, W, a, N, ei, E, epb);

    int nblk = (N + 1023) / 1024;
    scan1_kernel<<<nblk, 256>>>(N);
    scan2_kernel<<<1, 512>>>(nblk);
    scan3_kernel<<<(N + 255) / 256, 256>>>(N);

    long long half = (E + 1) / 2;
    weight_place_kernel<<<(unsigned int)((half + 255) / 256), 256>>>(ei, E);

    aggregate_kernel<<<(N * 32 + 255) / 256, 256>>>(out, N);
}